// round 1
// baseline (speedup 1.0000x reference)
#include <cuda_runtime.h>
#include <math.h>

#define B_   4
#define T_   2048
#define D_   1024
#define H_   16
#define HD_  64
#define M_   (B_ * T_)          // 8192 rows for projection GEMMs
#define SCALE_ 0.125f           // HD^-0.5

// ---------------- scratch (device globals; no allocation allowed) ----------
__device__ float g_q[(size_t)B_ * H_ * T_ * HD_];   // [B,H,T,Hd]
__device__ float g_k[(size_t)B_ * H_ * T_ * HD_];
__device__ float g_v[(size_t)B_ * H_ * T_ * HD_];
__device__ float g_attn[(size_t)B_ * T_ * D_];      // [B,T,D] pre-Wo

// ---------------------------------------------------------------------------
// GEMM: C = A @ W^T + bias.  A:[M,K] row-major, W:[N,K] row-major.
// M=8192, N=1024, K=1024. Tile 128x128x8, 256 threads, 8x8 per thread.
// layout==0: store C[m][n] to [B,H,T,Hd]  (n -> h*64+hd, m -> b*T+t)
// layout==1: store row-major C[m*N + n]
// ---------------------------------------------------------------------------
__global__ __launch_bounds__(256)
void gemm_nt(const float* __restrict__ A, const float* __restrict__ W,
             const float* __restrict__ bias, float* __restrict__ C, int layout)
{
    const int K = 1024;
    __shared__ float As[8 * 132];   // [k][m], padded row=132 floats
    __shared__ float Bs[8 * 132];   // [k][n]

    const int tid = threadIdx.x;
    const int m0 = blockIdx.y * 128;
    const int n0 = blockIdx.x * 128;
    const int tx = tid & 15;        // n sub-tile
    const int ty = tid >> 4;        // m sub-tile
    const int lrow = tid >> 1;      // 0..127
    const int lcol = (tid & 1) * 4; // 0 or 4

    const float* aptr = A + (size_t)(m0 + lrow) * K + lcol;
    const float* wptr = W + (size_t)(n0 + lrow) * K + lcol;

    float c[8][8] = {};

    for (int k0 = 0; k0 < K; k0 += 8) {
        __syncthreads();
        float4 av = *(const float4*)(aptr + k0);
        float4 wv = *(const float4*)(wptr + k0);
        As[(lcol + 0) * 132 + lrow] = av.x;
        As[(lcol + 1) * 132 + lrow] = av.y;
        As[(lcol + 2) * 132 + lrow] = av.z;
        As[(lcol + 3) * 132 + lrow] = av.w;
        Bs[(lcol + 0) * 132 + lrow] = wv.x;
        Bs[(lcol + 1) * 132 + lrow] = wv.y;
        Bs[(lcol + 2) * 132 + lrow] = wv.z;
        Bs[(lcol + 3) * 132 + lrow] = wv.w;
        __syncthreads();

        #pragma unroll
        for (int kk = 0; kk < 8; kk++) {
            float4 a0 = *(float4*)&As[kk * 132 + ty * 8];
            float4 a1 = *(float4*)&As[kk * 132 + ty * 8 + 4];
            float4 b0 = *(float4*)&Bs[kk * 132 + tx * 8];
            float4 b1 = *(float4*)&Bs[kk * 132 + tx * 8 + 4];
            float a[8] = {a0.x, a0.y, a0.z, a0.w, a1.x, a1.y, a1.z, a1.w};
            float b[8] = {b0.x, b0.y, b0.z, b0.w, b1.x, b1.y, b1.z, b1.w};
            #pragma unroll
            for (int i = 0; i < 8; i++)
                #pragma unroll
                for (int j = 0; j < 8; j++)
                    c[i][j] += a[i] * b[j];
        }
    }

    // epilogue
    #pragma unroll
    for (int i = 0; i < 8; i++) {
        int row = m0 + ty * 8 + i;
        #pragma unroll
        for (int jc = 0; jc < 8; jc += 4) {
            int col = n0 + tx * 8 + jc;
            float4 v;
            v.x = c[i][jc + 0] + bias[col + 0];
            v.y = c[i][jc + 1] + bias[col + 1];
            v.z = c[i][jc + 2] + bias[col + 2];
            v.w = c[i][jc + 3] + bias[col + 3];
            if (layout == 1) {
                *(float4*)(C + (size_t)row * 1024 + col) = v;
            } else {
                int b = row >> 11;          // / T_
                int t = row & 2047;
                int h = col >> 6;
                int hd = col & 63;
                *(float4*)(C + (((size_t)(b * H_ + h) * T_ + t) * HD_ + hd)) = v;
            }
        }
    }
}

// ---------------------------------------------------------------------------
// Flash attention (fp32, causal). One block = 64 query rows of one (b,h).
// 256 threads: thread (q = tid/4, g = tid%4) owns 16 keys (k = 4j+g) for
// scores/softmax and 16 output dims (d = g*16..g*16+15) for the PV accumulate.
// Quad (4-lane) shuffles handle row max/sum reductions and p broadcast.
// ---------------------------------------------------------------------------
#define BQ 64
#define BK 64
#define PAD 68   // 68 floats/row: 16B aligned & bank-conflict-free

__global__ __launch_bounds__(256)
void attn_kernel()
{
    extern __shared__ float sm[];
    float* Qs = sm;                 // [64][68]
    float* Ks = sm + 64 * PAD;
    float* Vs = sm + 2 * 64 * PAD;

    const int tid = threadIdx.x;
    const int q   = tid >> 2;
    const int g   = tid & 3;
    const int qtile = blockIdx.x;
    const int bh    = blockIdx.y;

    const float* qbase = g_q + (size_t)bh * T_ * HD_ + (size_t)qtile * BQ * HD_;
    const float* kbase = g_k + (size_t)bh * T_ * HD_;
    const float* vbase = g_v + (size_t)bh * T_ * HD_;

    // load Q tile (scaled)
    #pragma unroll
    for (int i = 0; i < 4; i++) {
        int n = tid + 256 * i;          // float4 index, 1024 total
        int row = n >> 4;
        int c4  = (n & 15) << 2;
        float4 v = *(const float4*)(qbase + row * HD_ + c4);
        float* dst = Qs + row * PAD + c4;
        dst[0] = v.x * SCALE_; dst[1] = v.y * SCALE_;
        dst[2] = v.z * SCALE_; dst[3] = v.w * SCALE_;
    }

    float acc[16];
    #pragma unroll
    for (int i = 0; i < 16; i++) acc[i] = 0.f;
    float m = -1e30f, l = 0.f;

    const int qglob = qtile * BQ + q;

    for (int kt = 0; kt <= qtile; kt++) {
        __syncthreads();
        const float* kp = kbase + (size_t)kt * BK * HD_;
        const float* vp = vbase + (size_t)kt * BK * HD_;
        #pragma unroll
        for (int i = 0; i < 4; i++) {
            int n = tid + 256 * i;
            int row = n >> 4;
            int c4  = (n & 15) << 2;
            *(float4*)(Ks + row * PAD + c4) = *(const float4*)(kp + row * HD_ + c4);
            *(float4*)(Vs + row * PAD + c4) = *(const float4*)(vp + row * HD_ + c4);
        }
        __syncthreads();

        // scores for 16 keys k = 4j+g
        float s[16];
        #pragma unroll
        for (int j = 0; j < 16; j++) s[j] = 0.f;
        #pragma unroll
        for (int d0 = 0; d0 < HD_; d0 += 4) {
            float4 qv = *(float4*)(Qs + q * PAD + d0);
            #pragma unroll
            for (int j = 0; j < 16; j++) {
                float4 kv = *(float4*)(Ks + (4 * j + g) * PAD + d0);
                s[j] += qv.x * kv.x + qv.y * kv.y + qv.z * kv.z + qv.w * kv.w;
            }
        }

        if (kt == qtile) {
            #pragma unroll
            for (int j = 0; j < 16; j++)
                if (kt * BK + 4 * j + g > qglob) s[j] = -1e30f;
        }

        // row max across quad
        float mloc = s[0];
        #pragma unroll
        for (int j = 1; j < 16; j++) mloc = fmaxf(mloc, s[j]);
        mloc = fmaxf(mloc, __shfl_xor_sync(0xffffffffu, mloc, 1));
        mloc = fmaxf(mloc, __shfl_xor_sync(0xffffffffu, mloc, 2));
        float mnew = fmaxf(m, mloc);
        float alpha = __expf(m - mnew);

        float psum = 0.f;
        #pragma unroll
        for (int j = 0; j < 16; j++) {
            s[j] = __expf(s[j] - mnew);
            psum += s[j];
        }
        psum += __shfl_xor_sync(0xffffffffu, psum, 1);
        psum += __shfl_xor_sync(0xffffffffu, psum, 2);
        l = l * alpha + psum;
        m = mnew;

        #pragma unroll
        for (int i = 0; i < 16; i++) acc[i] *= alpha;

        // PV: rounds over quad lanes; p broadcast via width-4 shuffle
        #pragma unroll
        for (int r = 0; r < 4; r++) {
            #pragma unroll
            for (int j = 0; j < 16; j++) {
                float p = __shfl_sync(0xffffffffu, s[j], r, 4);
                const float* vrow = Vs + (4 * j + r) * PAD + g * 16;
                #pragma unroll
                for (int dd = 0; dd < 16; dd += 4) {
                    float4 vv = *(float4*)(vrow + dd);
                    acc[dd + 0] += p * vv.x;
                    acc[dd + 1] += p * vv.y;
                    acc[dd + 2] += p * vv.z;
                    acc[dd + 3] += p * vv.w;
                }
            }
        }
    }

    // epilogue: write [B,T,D]
    float inv = 1.f / l;
    int b = bh / H_;
    int h = bh % H_;
    float* out = g_attn + ((size_t)(b * T_ + qglob)) * D_ + h * HD_ + g * 16;
    #pragma unroll
    for (int dd = 0; dd < 16; dd += 4) {
        float4 v;
        v.x = acc[dd + 0] * inv;
        v.y = acc[dd + 1] * inv;
        v.z = acc[dd + 2] * inv;
        v.w = acc[dd + 3] * inv;
        *(float4*)(out + dd) = v;
    }
}

// ---------------------------------------------------------------------------
extern "C" void kernel_launch(void* const* d_in, const int* in_sizes, int n_in,
                              void* d_out, int out_size)
{
    const float* query = (const float*)d_in[0];
    const float* key   = (const float*)d_in[1];
    const float* value = (const float*)d_in[2];
    const float* Wq    = (const float*)d_in[3];
    const float* bq    = (const float*)d_in[4];
    const float* Wk    = (const float*)d_in[5];
    const float* bk    = (const float*)d_in[6];
    const float* Wv    = (const float*)d_in[7];
    const float* bv    = (const float*)d_in[8];
    const float* Wo    = (const float*)d_in[9];
    const float* bo    = (const float*)d_in[10];
    float* out = (float*)d_out;

    float *qp, *kp, *vp, *ap;
    cudaGetSymbolAddress((void**)&qp, g_q);
    cudaGetSymbolAddress((void**)&kp, g_k);
    cudaGetSymbolAddress((void**)&vp, g_v);
    cudaGetSymbolAddress((void**)&ap, g_attn);

    dim3 ggrid(D_ / 128, M_ / 128);   // (8, 64)

    gemm_nt<<<ggrid, 256>>>(query, Wq, bq, qp, 0);
    gemm_nt<<<ggrid, 256>>>(key,   Wk, bk, kp, 0);
    gemm_nt<<<ggrid, 256>>>(value, Wv, bv, vp, 0);

    size_t attn_smem = (size_t)3 * 64 * PAD * sizeof(float);  // 52224 B
    cudaFuncSetAttribute(attn_kernel, cudaFuncAttributeMaxDynamicSharedMemorySize,
                         (int)attn_smem);
    attn_kernel<<<dim3(T_ / BQ, B_ * H_), 256, attn_smem>>>();

    gemm_nt<<<ggrid, 256>>>(ap, Wo, bo, out, 1);
}

// round 3
// speedup vs baseline: 1.2789x; 1.2789x over previous
#include <cuda_runtime.h>
#include <cuda_bf16.h>
#include <math.h>
#include <stdint.h>

#define B_   4
#define T_   2048
#define D_   1024
#define H_   16
#define HD_  64
#define M_   (B_ * T_)
#define SCALE_ 0.125f

// ---------------- scratch (device globals; no allocation allowed) ----------
__device__ float g_q[(size_t)B_ * H_ * T_ * HD_];   // [B,H,T,Hd]
__device__ float g_k[(size_t)B_ * H_ * T_ * HD_];
__device__ float g_v[(size_t)B_ * H_ * T_ * HD_];
__device__ float g_attn[(size_t)B_ * T_ * D_];      // [B,T,D] pre-Wo

// ---------------------------------------------------------------------------
// bf16-split tensor-core GEMM (portable mma.sync, no tcgen05):
//   C[M,N] = A[M,K] @ W[N,K]^T + bias,  M=8192, N=K=1024, fp32 in/out.
// Split: a = ah + al (bf16 each); D += ah*wh + ah*wl + al*wh.
// CTA: 128x128 tile, 8 warps (4x2), warp tile 32x64, K-chunk 32, dbl-buffered.
// layout==0: scatter to [B,H,T,Hd];  layout==1: row-major.
// ---------------------------------------------------------------------------
#define LDB 40                       // bf16 units per smem row (80B, padded)
#define BUF_ELEMS (128 * LDB)        // one matrix buffer (bf16 units)
#define STAGE_ELEMS (4 * BUF_ELEMS)  // Ah, Al, Wh, Wl
#define GEMM_SMEM (2 * STAGE_ELEMS * 2)  // bytes: 2 stages * 4 bufs * 10240B

__device__ __forceinline__ void mma_bf16(
    float& c0, float& c1, float& c2, float& c3,
    uint32_t a0, uint32_t a1, uint32_t a2, uint32_t a3,
    uint32_t b0, uint32_t b1)
{
    asm volatile(
        "mma.sync.aligned.m16n8k16.row.col.f32.bf16.bf16.f32 "
        "{%0,%1,%2,%3}, {%4,%5,%6,%7}, {%8,%9}, {%0,%1,%2,%3};"
        : "+f"(c0), "+f"(c1), "+f"(c2), "+f"(c3)
        : "r"(a0), "r"(a1), "r"(a2), "r"(a3), "r"(b0), "r"(b1));
}

__global__ __launch_bounds__(256)
void gemm_mma(const float* __restrict__ A, const float* __restrict__ W,
              const float* __restrict__ bias, float* __restrict__ C, int layout)
{
    extern __shared__ __nv_bfloat16 sm_g[];

    const int tid = threadIdx.x;
    const int wid = tid >> 5;
    const int lane = tid & 31;
    const int group = lane >> 2;     // 0..7
    const int tg = lane & 3;         // 0..3
    const int wm = wid >> 1;         // 0..3  (m offset /32)
    const int wn = wid & 1;          // 0..1  (n offset /64)
    const int m0 = blockIdx.y * 128;
    const int n0 = blockIdx.x * 128;

    // per-thread gmem load coords (4 float4 per matrix per chunk)
    int lrow[4], lc4[4];
    #pragma unroll
    for (int i = 0; i < 4; i++) {
        int idx = tid + 256 * i;     // 0..1023
        lrow[i] = idx >> 3;          // 0..127
        lc4[i]  = (idx & 7) * 4;     // fp32 col within 32-wide chunk
    }

    float c[2][8][4];
    #pragma unroll
    for (int mt = 0; mt < 2; mt++)
        #pragma unroll
        for (int nt = 0; nt < 8; nt++)
            #pragma unroll
            for (int r = 0; r < 4; r++) c[mt][nt][r] = 0.f;

    float4 pa[4], pw[4];
    // prefetch chunk 0
    #pragma unroll
    for (int i = 0; i < 4; i++) {
        pa[i] = *(const float4*)(A + (size_t)(m0 + lrow[i]) * 1024 + lc4[i]);
        pw[i] = *(const float4*)(W + (size_t)(n0 + lrow[i]) * 1024 + lc4[i]);
    }

    for (int chunk = 0; chunk < 32; chunk++) {
        __nv_bfloat16* stage = sm_g + (chunk & 1) * STAGE_ELEMS;
        __nv_bfloat16* sAh = stage;
        __nv_bfloat16* sAl = stage + BUF_ELEMS;
        __nv_bfloat16* sWh = stage + 2 * BUF_ELEMS;
        __nv_bfloat16* sWl = stage + 3 * BUF_ELEMS;

        // split + store prefetched regs to smem
        #pragma unroll
        for (int i = 0; i < 4; i++) {
            int off = lrow[i] * LDB + lc4[i];
            {
                __nv_bfloat162 h0 = __floats2bfloat162_rn(pa[i].x, pa[i].y);
                __nv_bfloat162 h1 = __floats2bfloat162_rn(pa[i].z, pa[i].w);
                float2 f0 = __bfloat1622float2(h0);
                float2 f1 = __bfloat1622float2(h1);
                __nv_bfloat162 l0 = __floats2bfloat162_rn(pa[i].x - f0.x, pa[i].y - f0.y);
                __nv_bfloat162 l1 = __floats2bfloat162_rn(pa[i].z - f1.x, pa[i].w - f1.y);
                *(uint2*)(sAh + off) = make_uint2(*(uint32_t*)&h0, *(uint32_t*)&h1);
                *(uint2*)(sAl + off) = make_uint2(*(uint32_t*)&l0, *(uint32_t*)&l1);
            }
            {
                __nv_bfloat162 h0 = __floats2bfloat162_rn(pw[i].x, pw[i].y);
                __nv_bfloat162 h1 = __floats2bfloat162_rn(pw[i].z, pw[i].w);
                float2 f0 = __bfloat1622float2(h0);
                float2 f1 = __bfloat1622float2(h1);
                __nv_bfloat162 l0 = __floats2bfloat162_rn(pw[i].x - f0.x, pw[i].y - f0.y);
                __nv_bfloat162 l1 = __floats2bfloat162_rn(pw[i].z - f1.x, pw[i].w - f1.y);
                *(uint2*)(sWh + off) = make_uint2(*(uint32_t*)&h0, *(uint32_t*)&h1);
                *(uint2*)(sWl + off) = make_uint2(*(uint32_t*)&l0, *(uint32_t*)&l1);
            }
        }
        __syncthreads();

        // prefetch next chunk
        if (chunk < 31) {
            const int k0 = (chunk + 1) * 32;
            #pragma unroll
            for (int i = 0; i < 4; i++) {
                pa[i] = *(const float4*)(A + (size_t)(m0 + lrow[i]) * 1024 + k0 + lc4[i]);
                pw[i] = *(const float4*)(W + (size_t)(n0 + lrow[i]) * 1024 + k0 + lc4[i]);
            }
        }

        // compute on this stage: 2 k16 steps
        #pragma unroll
        for (int ks = 0; ks < 2; ks++) {
            const int koff = ks * 16;
            uint32_t ah[2][4], al[2][4];
            #pragma unroll
            for (int mt = 0; mt < 2; mt++) {
                int r0 = wm * 32 + mt * 16 + group;
                int cA = koff + 2 * tg;
                ah[mt][0] = *(uint32_t*)(sAh + r0 * LDB + cA);
                ah[mt][1] = *(uint32_t*)(sAh + (r0 + 8) * LDB + cA);
                ah[mt][2] = *(uint32_t*)(sAh + r0 * LDB + cA + 8);
                ah[mt][3] = *(uint32_t*)(sAh + (r0 + 8) * LDB + cA + 8);
                al[mt][0] = *(uint32_t*)(sAl + r0 * LDB + cA);
                al[mt][1] = *(uint32_t*)(sAl + (r0 + 8) * LDB + cA);
                al[mt][2] = *(uint32_t*)(sAl + r0 * LDB + cA + 8);
                al[mt][3] = *(uint32_t*)(sAl + (r0 + 8) * LDB + cA + 8);
            }
            #pragma unroll
            for (int nt = 0; nt < 8; nt++) {
                int rn = wn * 64 + nt * 8 + group;
                int cB = koff + 2 * tg;
                uint32_t bh0 = *(uint32_t*)(sWh + rn * LDB + cB);
                uint32_t bh1 = *(uint32_t*)(sWh + rn * LDB + cB + 8);
                uint32_t bl0 = *(uint32_t*)(sWl + rn * LDB + cB);
                uint32_t bl1 = *(uint32_t*)(sWl + rn * LDB + cB + 8);
                #pragma unroll
                for (int mt = 0; mt < 2; mt++) {
                    float* cc = c[mt][nt];
                    mma_bf16(cc[0], cc[1], cc[2], cc[3],
                             ah[mt][0], ah[mt][1], ah[mt][2], ah[mt][3], bh0, bh1);
                    mma_bf16(cc[0], cc[1], cc[2], cc[3],
                             ah[mt][0], ah[mt][1], ah[mt][2], ah[mt][3], bl0, bl1);
                    mma_bf16(cc[0], cc[1], cc[2], cc[3],
                             al[mt][0], al[mt][1], al[mt][2], al[mt][3], bh0, bh1);
                }
            }
        }
        __syncthreads();
    }

    // epilogue: bias + scatter store (float2 per c-pair)
    #pragma unroll
    for (int mt = 0; mt < 2; mt++) {
        #pragma unroll
        for (int nt = 0; nt < 8; nt++) {
            int col = n0 + wn * 64 + nt * 8 + 2 * tg;
            float bx = bias[col], by = bias[col + 1];
            #pragma unroll
            for (int half = 0; half < 2; half++) {
                int row = m0 + wm * 32 + mt * 16 + group + half * 8;
                float2 v;
                v.x = c[mt][nt][half * 2 + 0] + bx;
                v.y = c[mt][nt][half * 2 + 1] + by;
                if (layout == 1) {
                    *(float2*)(C + (size_t)row * 1024 + col) = v;
                } else {
                    int b = row >> 11;
                    int t = row & 2047;
                    int h = col >> 6;
                    int hd = col & 63;
                    *(float2*)(C + (((size_t)(b * H_ + h) * T_ + t) * HD_ + hd)) = v;
                }
            }
        }
    }
}

// ---------------------------------------------------------------------------
// Flash attention (fp32, causal) — unchanged known-correct version.
// ---------------------------------------------------------------------------
#define BQ 64
#define BK 64
#define PAD 68

__global__ __launch_bounds__(256)
void attn_kernel()
{
    extern __shared__ float sm[];
    float* Qs = sm;                 // [64][68]
    float* Ks = sm + 64 * PAD;
    float* Vs = sm + 2 * 64 * PAD;

    const int tid = threadIdx.x;
    const int q   = tid >> 2;
    const int g   = tid & 3;
    const int qtile = blockIdx.x;
    const int bh    = blockIdx.y;

    const float* qbase = g_q + (size_t)bh * T_ * HD_ + (size_t)qtile * BQ * HD_;
    const float* kbase = g_k + (size_t)bh * T_ * HD_;
    const float* vbase = g_v + (size_t)bh * T_ * HD_;

    #pragma unroll
    for (int i = 0; i < 4; i++) {
        int n = tid + 256 * i;
        int row = n >> 4;
        int c4  = (n & 15) << 2;
        float4 v = *(const float4*)(qbase + row * HD_ + c4);
        float* dst = Qs + row * PAD + c4;
        dst[0] = v.x * SCALE_; dst[1] = v.y * SCALE_;
        dst[2] = v.z * SCALE_; dst[3] = v.w * SCALE_;
    }

    float acc[16];
    #pragma unroll
    for (int i = 0; i < 16; i++) acc[i] = 0.f;
    float m = -1e30f, l = 0.f;

    const int qglob = qtile * BQ + q;

    for (int kt = 0; kt <= qtile; kt++) {
        __syncthreads();
        const float* kp = kbase + (size_t)kt * BK * HD_;
        const float* vp = vbase + (size_t)kt * BK * HD_;
        #pragma unroll
        for (int i = 0; i < 4; i++) {
            int n = tid + 256 * i;
            int row = n >> 4;
            int c4  = (n & 15) << 2;
            *(float4*)(Ks + row * PAD + c4) = *(const float4*)(kp + row * HD_ + c4);
            *(float4*)(Vs + row * PAD + c4) = *(const float4*)(vp + row * HD_ + c4);
        }
        __syncthreads();

        float s[16];
        #pragma unroll
        for (int j = 0; j < 16; j++) s[j] = 0.f;
        #pragma unroll
        for (int d0 = 0; d0 < HD_; d0 += 4) {
            float4 qv = *(float4*)(Qs + q * PAD + d0);
            #pragma unroll
            for (int j = 0; j < 16; j++) {
                float4 kv = *(float4*)(Ks + (4 * j + g) * PAD + d0);
                s[j] += qv.x * kv.x + qv.y * kv.y + qv.z * kv.z + qv.w * kv.w;
            }
        }

        if (kt == qtile) {
            #pragma unroll
            for (int j = 0; j < 16; j++)
                if (kt * BK + 4 * j + g > qglob) s[j] = -1e30f;
        }

        float mloc = s[0];
        #pragma unroll
        for (int j = 1; j < 16; j++) mloc = fmaxf(mloc, s[j]);
        mloc = fmaxf(mloc, __shfl_xor_sync(0xffffffffu, mloc, 1));
        mloc = fmaxf(mloc, __shfl_xor_sync(0xffffffffu, mloc, 2));
        float mnew = fmaxf(m, mloc);
        float alpha = __expf(m - mnew);

        float psum = 0.f;
        #pragma unroll
        for (int j = 0; j < 16; j++) {
            s[j] = __expf(s[j] - mnew);
            psum += s[j];
        }
        psum += __shfl_xor_sync(0xffffffffu, psum, 1);
        psum += __shfl_xor_sync(0xffffffffu, psum, 2);
        l = l * alpha + psum;
        m = mnew;

        #pragma unroll
        for (int i = 0; i < 16; i++) acc[i] *= alpha;

        #pragma unroll
        for (int r = 0; r < 4; r++) {
            #pragma unroll
            for (int j = 0; j < 16; j++) {
                float p = __shfl_sync(0xffffffffu, s[j], r, 4);
                const float* vrow = Vs + (4 * j + r) * PAD + g * 16;
                #pragma unroll
                for (int dd = 0; dd < 16; dd += 4) {
                    float4 vv = *(float4*)(vrow + dd);
                    acc[dd + 0] += p * vv.x;
                    acc[dd + 1] += p * vv.y;
                    acc[dd + 2] += p * vv.z;
                    acc[dd + 3] += p * vv.w;
                }
            }
        }
    }

    float inv = 1.f / l;
    int b = bh / H_;
    int h = bh % H_;
    float* out = g_attn + ((size_t)(b * T_ + qglob)) * D_ + h * HD_ + g * 16;
    #pragma unroll
    for (int dd = 0; dd < 16; dd += 4) {
        float4 v;
        v.x = acc[dd + 0] * inv;
        v.y = acc[dd + 1] * inv;
        v.z = acc[dd + 2] * inv;
        v.w = acc[dd + 3] * inv;
        *(float4*)(out + dd) = v;
    }
}

// ---------------------------------------------------------------------------
extern "C" void kernel_launch(void* const* d_in, const int* in_sizes, int n_in,
                              void* d_out, int out_size)
{
    const float* query = (const float*)d_in[0];
    const float* key   = (const float*)d_in[1];
    const float* value = (const float*)d_in[2];
    const float* Wq    = (const float*)d_in[3];
    const float* bq    = (const float*)d_in[4];
    const float* Wk    = (const float*)d_in[5];
    const float* bk    = (const float*)d_in[6];
    const float* Wv    = (const float*)d_in[7];
    const float* bv    = (const float*)d_in[8];
    const float* Wo    = (const float*)d_in[9];
    const float* bo    = (const float*)d_in[10];
    float* out = (float*)d_out;

    float *qp, *kp, *vp, *ap;
    cudaGetSymbolAddress((void**)&qp, g_q);
    cudaGetSymbolAddress((void**)&kp, g_k);
    cudaGetSymbolAddress((void**)&vp, g_v);
    cudaGetSymbolAddress((void**)&ap, g_attn);

    cudaFuncSetAttribute(gemm_mma, cudaFuncAttributeMaxDynamicSharedMemorySize,
                         GEMM_SMEM);

    dim3 ggrid(D_ / 128, M_ / 128);   // (8, 64)

    gemm_mma<<<ggrid, 256, GEMM_SMEM>>>(query, Wq, bq, qp, 0);
    gemm_mma<<<ggrid, 256, GEMM_SMEM>>>(key,   Wk, bk, kp, 0);
    gemm_mma<<<ggrid, 256, GEMM_SMEM>>>(value, Wv, bv, vp, 0);

    size_t attn_smem = (size_t)3 * 64 * PAD * sizeof(float);  // 52224 B
    cudaFuncSetAttribute(attn_kernel, cudaFuncAttributeMaxDynamicSharedMemorySize,
                         (int)attn_smem);
    attn_kernel<<<dim3(T_ / BQ, B_ * H_), 256, attn_smem>>>();

    gemm_mma<<<ggrid, 256, GEMM_SMEM>>>(ap, Wo, bo, out, 1);
}

// round 4
// speedup vs baseline: 4.5897x; 3.5888x over previous
#include <cuda_runtime.h>
#include <cuda_bf16.h>
#include <math.h>
#include <stdint.h>

#define B_   4
#define T_   2048
#define D_   1024
#define H_   16
#define HD_  64
#define M_   (B_ * T_)
#define SCALE_ 0.125f

// ---------------- scratch (device globals; no allocation allowed) ----------
__device__ __nv_bfloat16 g_qh[(size_t)B_ * H_ * T_ * HD_];  // [B,H,T,Hd] hi
__device__ __nv_bfloat16 g_ql[(size_t)B_ * H_ * T_ * HD_];  // lo
__device__ __nv_bfloat16 g_kh[(size_t)B_ * H_ * T_ * HD_];
__device__ __nv_bfloat16 g_kl[(size_t)B_ * H_ * T_ * HD_];
__device__ __nv_bfloat16 g_vh[(size_t)B_ * H_ * T_ * HD_];
__device__ __nv_bfloat16 g_vl[(size_t)B_ * H_ * T_ * HD_];
__device__ float g_attn[(size_t)B_ * T_ * D_];              // [B,T,D] pre-Wo

// =========================== helpers ========================================
__device__ __forceinline__ uint32_t smem_u32(const void* p) {
    uint32_t a;
    asm("{ .reg .u64 t; cvta.to.shared.u64 t, %1; cvt.u32.u64 %0, t; }"
        : "=r"(a) : "l"(p));
    return a;
}

__device__ __forceinline__ void mma_bf16(
    float& c0, float& c1, float& c2, float& c3,
    uint32_t a0, uint32_t a1, uint32_t a2, uint32_t a3,
    uint32_t b0, uint32_t b1)
{
    asm volatile(
        "mma.sync.aligned.m16n8k16.row.col.f32.bf16.bf16.f32 "
        "{%0,%1,%2,%3}, {%4,%5,%6,%7}, {%8,%9}, {%0,%1,%2,%3};"
        : "+f"(c0), "+f"(c1), "+f"(c2), "+f"(c3)
        : "r"(a0), "r"(a1), "r"(a2), "r"(a3), "r"(b0), "r"(b1));
}

__device__ __forceinline__ uint32_t lds32(uint32_t a) {
    uint32_t v;
    asm volatile("ld.shared.b32 %0, [%1];" : "=r"(v) : "r"(a));
    return v;
}

__device__ __forceinline__ void ldmx4t(uint32_t* r, uint32_t a) {
    asm volatile(
        "ldmatrix.sync.aligned.m8n8.x4.trans.shared.b16 {%0,%1,%2,%3}, [%4];"
        : "=r"(r[0]), "=r"(r[1]), "=r"(r[2]), "=r"(r[3]) : "r"(a));
}

__device__ __forceinline__ void cp16(uint32_t dst, const void* src) {
    asm volatile("cp.async.cg.shared.global [%0], [%1], 16;"
                 :: "r"(dst), "l"(src));
}
#define CP_COMMIT() asm volatile("cp.async.commit_group;" ::: "memory")
#define CP_WAIT1()  asm volatile("cp.async.wait_group 1;" ::: "memory")
#define CP_WAIT0()  asm volatile("cp.async.wait_group 0;" ::: "memory")

// split x,y into bf16 hi pair + bf16 lo pair (packed u32, low half = x)
__device__ __forceinline__ void split_pack(float x, float y,
                                           uint32_t& hi, uint32_t& lo) {
    __nv_bfloat162 h = __floats2bfloat162_rn(x, y);
    float2 f = __bfloat1622float2(h);
    __nv_bfloat162 l = __floats2bfloat162_rn(x - f.x, y - f.y);
    hi = *(uint32_t*)&h;
    lo = *(uint32_t*)&l;
}

// ---------------------------------------------------------------------------
// bf16-split tensor-core GEMM: C = A[M,K] @ W[N,K]^T + bias.
// layout==0: write (C+bias)*scale as split bf16 hi/lo to [B,H,T,Hd] arrays.
// layout==1: write fp32 row-major to Cf.
// ---------------------------------------------------------------------------
#define LDB 40
#define BUF_ELEMS (128 * LDB)
#define STAGE_ELEMS (4 * BUF_ELEMS)
#define GEMM_SMEM (2 * STAGE_ELEMS * 2)

__global__ __launch_bounds__(256)
void gemm_mma(const float* __restrict__ A, const float* __restrict__ W,
              const float* __restrict__ bias,
              __nv_bfloat16* __restrict__ Chi, __nv_bfloat16* __restrict__ Clo,
              float* __restrict__ Cf, int layout, float scale)
{
    extern __shared__ __nv_bfloat16 sm_g[];

    const int tid = threadIdx.x;
    const int wid = tid >> 5;
    const int lane = tid & 31;
    const int group = lane >> 2;
    const int tg = lane & 3;
    const int wm = wid >> 1;
    const int wn = wid & 1;
    const int m0 = blockIdx.y * 128;
    const int n0 = blockIdx.x * 128;

    int lrow[4], lc4[4];
    #pragma unroll
    for (int i = 0; i < 4; i++) {
        int idx = tid + 256 * i;
        lrow[i] = idx >> 3;
        lc4[i]  = (idx & 7) * 4;
    }

    float c[2][8][4];
    #pragma unroll
    for (int mt = 0; mt < 2; mt++)
        #pragma unroll
        for (int nt = 0; nt < 8; nt++)
            #pragma unroll
            for (int r = 0; r < 4; r++) c[mt][nt][r] = 0.f;

    float4 pa[4], pw[4];
    #pragma unroll
    for (int i = 0; i < 4; i++) {
        pa[i] = *(const float4*)(A + (size_t)(m0 + lrow[i]) * 1024 + lc4[i]);
        pw[i] = *(const float4*)(W + (size_t)(n0 + lrow[i]) * 1024 + lc4[i]);
    }

    for (int chunk = 0; chunk < 32; chunk++) {
        __nv_bfloat16* stage = sm_g + (chunk & 1) * STAGE_ELEMS;
        __nv_bfloat16* sAh = stage;
        __nv_bfloat16* sAl = stage + BUF_ELEMS;
        __nv_bfloat16* sWh = stage + 2 * BUF_ELEMS;
        __nv_bfloat16* sWl = stage + 3 * BUF_ELEMS;

        #pragma unroll
        for (int i = 0; i < 4; i++) {
            int off = lrow[i] * LDB + lc4[i];
            {
                uint32_t h0, h1, l0, l1;
                split_pack(pa[i].x, pa[i].y, h0, l0);
                split_pack(pa[i].z, pa[i].w, h1, l1);
                *(uint2*)(sAh + off) = make_uint2(h0, h1);
                *(uint2*)(sAl + off) = make_uint2(l0, l1);
            }
            {
                uint32_t h0, h1, l0, l1;
                split_pack(pw[i].x, pw[i].y, h0, l0);
                split_pack(pw[i].z, pw[i].w, h1, l1);
                *(uint2*)(sWh + off) = make_uint2(h0, h1);
                *(uint2*)(sWl + off) = make_uint2(l0, l1);
            }
        }
        __syncthreads();

        if (chunk < 31) {
            const int k0 = (chunk + 1) * 32;
            #pragma unroll
            for (int i = 0; i < 4; i++) {
                pa[i] = *(const float4*)(A + (size_t)(m0 + lrow[i]) * 1024 + k0 + lc4[i]);
                pw[i] = *(const float4*)(W + (size_t)(n0 + lrow[i]) * 1024 + k0 + lc4[i]);
            }
        }

        #pragma unroll
        for (int ks = 0; ks < 2; ks++) {
            const int koff = ks * 16;
            uint32_t ah[2][4], al[2][4];
            #pragma unroll
            for (int mt = 0; mt < 2; mt++) {
                int r0 = wm * 32 + mt * 16 + group;
                int cA = koff + 2 * tg;
                ah[mt][0] = *(uint32_t*)(sAh + r0 * LDB + cA);
                ah[mt][1] = *(uint32_t*)(sAh + (r0 + 8) * LDB + cA);
                ah[mt][2] = *(uint32_t*)(sAh + r0 * LDB + cA + 8);
                ah[mt][3] = *(uint32_t*)(sAh + (r0 + 8) * LDB + cA + 8);
                al[mt][0] = *(uint32_t*)(sAl + r0 * LDB + cA);
                al[mt][1] = *(uint32_t*)(sAl + (r0 + 8) * LDB + cA);
                al[mt][2] = *(uint32_t*)(sAl + r0 * LDB + cA + 8);
                al[mt][3] = *(uint32_t*)(sAl + (r0 + 8) * LDB + cA + 8);
            }
            #pragma unroll
            for (int nt = 0; nt < 8; nt++) {
                int rn = wn * 64 + nt * 8 + group;
                int cB = koff + 2 * tg;
                uint32_t bh0 = *(uint32_t*)(sWh + rn * LDB + cB);
                uint32_t bh1 = *(uint32_t*)(sWh + rn * LDB + cB + 8);
                uint32_t bl0 = *(uint32_t*)(sWl + rn * LDB + cB);
                uint32_t bl1 = *(uint32_t*)(sWl + rn * LDB + cB + 8);
                #pragma unroll
                for (int mt = 0; mt < 2; mt++) {
                    float* cc = c[mt][nt];
                    mma_bf16(cc[0], cc[1], cc[2], cc[3],
                             ah[mt][0], ah[mt][1], ah[mt][2], ah[mt][3], bh0, bh1);
                    mma_bf16(cc[0], cc[1], cc[2], cc[3],
                             ah[mt][0], ah[mt][1], ah[mt][2], ah[mt][3], bl0, bl1);
                    mma_bf16(cc[0], cc[1], cc[2], cc[3],
                             al[mt][0], al[mt][1], al[mt][2], al[mt][3], bh0, bh1);
                }
            }
        }
        __syncthreads();
    }

    // epilogue
    #pragma unroll
    for (int mt = 0; mt < 2; mt++) {
        #pragma unroll
        for (int nt = 0; nt < 8; nt++) {
            int col = n0 + wn * 64 + nt * 8 + 2 * tg;
            float bx = bias[col], by = bias[col + 1];
            #pragma unroll
            for (int half = 0; half < 2; half++) {
                int row = m0 + wm * 32 + mt * 16 + group + half * 8;
                float vx = c[mt][nt][half * 2 + 0] + bx;
                float vy = c[mt][nt][half * 2 + 1] + by;
                if (layout == 1) {
                    *(float2*)(Cf + (size_t)row * 1024 + col) = make_float2(vx, vy);
                } else {
                    vx *= scale; vy *= scale;
                    int b = row >> 11;
                    int t = row & 2047;
                    int h = col >> 6;
                    int hd = col & 63;
                    size_t addr = ((size_t)(b * H_ + h) * T_ + t) * HD_ + hd;
                    uint32_t hi, lo;
                    split_pack(vx, vy, hi, lo);
                    *(uint32_t*)(Chi + addr) = hi;
                    *(uint32_t*)(Clo + addr) = lo;
                }
            }
        }
    }
}

// ---------------------------------------------------------------------------
// Tensor-core flash attention (causal).
// CTA: 128 q-rows of one (b,h). 8 warps x 16 rows. K-tiles of 64 keys,
// cp.async double-buffered bf16 hi/lo K and V tiles.
// S and PV via mma.sync bf16 with 3-term splits. ldmatrix.trans for V.
// ---------------------------------------------------------------------------
#define AT_ROWB 144                 // 64 bf16 padded to 72 => 144 bytes/row
#define AT_TILE (64 * AT_ROWB)      // 9216 B per array
#define AT_STAGE (4 * AT_TILE)      // Kh,Kl,Vh,Vl = 36864 B
#define AT_SMEM (2 * AT_STAGE)      // 73728 B

__global__ __launch_bounds__(256, 1)
void attn_mma()
{
    extern __shared__ char smraw[];
    const uint32_t smb = smem_u32(smraw);
    const int tid = threadIdx.x;
    const int w = tid >> 5;
    const int lane = tid & 31;
    const int g = lane >> 2;
    const int tg = lane & 3;
    const int qt = 15 - blockIdx.x;        // heavy tiles first
    const int bh = blockIdx.y;
    const int b = bh >> 4;
    const int h = bh & 15;

    const int r0 = qt * 128 + w * 16 + g;  // rows r0 and r0+8

    // ---- Q fragments (A operand), hi/lo, direct from gmem ----
    const __nv_bfloat16* qhp = g_qh + (size_t)bh * T_ * HD_;
    const __nv_bfloat16* qlp = g_ql + (size_t)bh * T_ * HD_;
    uint32_t qfh[4][4], qfl[4][4];
    #pragma unroll
    for (int ks = 0; ks < 4; ks++) {
        int d = ks * 16 + 2 * tg;
        size_t a0 = (size_t)r0 * HD_ + d;
        size_t a1 = (size_t)(r0 + 8) * HD_ + d;
        qfh[ks][0] = *(const uint32_t*)(qhp + a0);
        qfh[ks][1] = *(const uint32_t*)(qhp + a1);
        qfh[ks][2] = *(const uint32_t*)(qhp + a0 + 8);
        qfh[ks][3] = *(const uint32_t*)(qhp + a1 + 8);
        qfl[ks][0] = *(const uint32_t*)(qlp + a0);
        qfl[ks][1] = *(const uint32_t*)(qlp + a1);
        qfl[ks][2] = *(const uint32_t*)(qlp + a0 + 8);
        qfl[ks][3] = *(const uint32_t*)(qlp + a1 + 8);
    }

    const __nv_bfloat16* khp = g_kh + (size_t)bh * T_ * HD_;
    const __nv_bfloat16* klp = g_kl + (size_t)bh * T_ * HD_;
    const __nv_bfloat16* vhp = g_vh + (size_t)bh * T_ * HD_;
    const __nv_bfloat16* vlp = g_vl + (size_t)bh * T_ * HD_;

    float o[8][4];
    #pragma unroll
    for (int j = 0; j < 8; j++)
        #pragma unroll
        for (int r = 0; r < 4; r++) o[j][r] = 0.f;
    float m0 = -1e30f, m1 = -1e30f, l0 = 0.f, l1 = 0.f;

    const int nkt = 2 * qt + 2;
    const int last_kt = (qt * 128 + w * 16 + 15) >> 6;

    // tile loader: 4 arrays x 64 rows x 128B via cp.async (8 x 16B per thread)
    #define LOAD_TILE(KT, S) do {                                              \
        uint32_t dbase = smb + (S) * AT_STAGE;                                 \
        size_t toff = (size_t)(KT) * 64 * HD_;                                 \
        _Pragma("unroll")                                                      \
        for (int i = 0; i < 8; i++) {                                          \
            const __nv_bfloat16* sp = (i < 2) ? khp : (i < 4) ? klp            \
                                     : (i < 6) ? vhp : vlp;                    \
            int a = i >> 1;                                                    \
            int rem = ((i & 1) << 8) + tid;                                    \
            int row = rem >> 3, ch = rem & 7;                                  \
            cp16(dbase + a * AT_TILE + row * AT_ROWB + ch * 16,                \
                 sp + toff + (size_t)row * HD_ + ch * 8);                      \
        }                                                                      \
    } while (0)

    LOAD_TILE(0, 0);
    CP_COMMIT();

    for (int kt = 0; kt < nkt; kt++) {
        if (kt + 1 < nkt) {
            LOAD_TILE(kt + 1, (kt + 1) & 1);
            CP_COMMIT();
            CP_WAIT1();
        } else {
            CP_WAIT0();
        }
        __syncthreads();

        if (kt <= last_kt) {
            const uint32_t Kh = smb + (kt & 1) * AT_STAGE;
            const uint32_t Vh = Kh + 2 * AT_TILE;

            // ---- S = Q K^T (3-term split) ----
            float sc[8][4];
            #pragma unroll
            for (int j = 0; j < 8; j++)
                #pragma unroll
                for (int r = 0; r < 4; r++) sc[j][r] = 0.f;

            #pragma unroll
            for (int ks = 0; ks < 4; ks++) {
                #pragma unroll
                for (int j = 0; j < 8; j++) {
                    uint32_t ka = Kh + (8 * j + g) * AT_ROWB + (16 * ks + 2 * tg) * 2;
                    uint32_t bh0 = lds32(ka);
                    uint32_t bh1 = lds32(ka + 16);
                    uint32_t bl0 = lds32(ka + AT_TILE);
                    uint32_t bl1 = lds32(ka + AT_TILE + 16);
                    float* cc = sc[j];
                    mma_bf16(cc[0], cc[1], cc[2], cc[3],
                             qfh[ks][0], qfh[ks][1], qfh[ks][2], qfh[ks][3], bh0, bh1);
                    mma_bf16(cc[0], cc[1], cc[2], cc[3],
                             qfh[ks][0], qfh[ks][1], qfh[ks][2], qfh[ks][3], bl0, bl1);
                    mma_bf16(cc[0], cc[1], cc[2], cc[3],
                             qfl[ks][0], qfl[ks][1], qfl[ks][2], qfl[ks][3], bh0, bh1);
                }
            }

            // ---- causal mask (only diagonal tile of this warp) ----
            if (kt == last_kt) {
                #pragma unroll
                for (int j = 0; j < 8; j++) {
                    int cgl = kt * 64 + 8 * j + 2 * tg;
                    if (cgl     > r0)     sc[j][0] = -1e30f;
                    if (cgl + 1 > r0)     sc[j][1] = -1e30f;
                    if (cgl     > r0 + 8) sc[j][2] = -1e30f;
                    if (cgl + 1 > r0 + 8) sc[j][3] = -1e30f;
                }
            }

            // ---- online softmax ----
            float mx0 = -1e30f, mx1 = -1e30f;
            #pragma unroll
            for (int j = 0; j < 8; j++) {
                mx0 = fmaxf(mx0, fmaxf(sc[j][0], sc[j][1]));
                mx1 = fmaxf(mx1, fmaxf(sc[j][2], sc[j][3]));
            }
            mx0 = fmaxf(mx0, __shfl_xor_sync(0xffffffffu, mx0, 1));
            mx0 = fmaxf(mx0, __shfl_xor_sync(0xffffffffu, mx0, 2));
            mx1 = fmaxf(mx1, __shfl_xor_sync(0xffffffffu, mx1, 1));
            mx1 = fmaxf(mx1, __shfl_xor_sync(0xffffffffu, mx1, 2));
            float mn0 = fmaxf(m0, mx0), mn1 = fmaxf(m1, mx1);
            float al0 = __expf(m0 - mn0), al1 = __expf(m1 - mn1);
            float ps0 = 0.f, ps1 = 0.f;
            #pragma unroll
            for (int j = 0; j < 8; j++) {
                sc[j][0] = __expf(sc[j][0] - mn0);
                sc[j][1] = __expf(sc[j][1] - mn0);
                sc[j][2] = __expf(sc[j][2] - mn1);
                sc[j][3] = __expf(sc[j][3] - mn1);
                ps0 += sc[j][0] + sc[j][1];
                ps1 += sc[j][2] + sc[j][3];
            }
            ps0 += __shfl_xor_sync(0xffffffffu, ps0, 1);
            ps0 += __shfl_xor_sync(0xffffffffu, ps0, 2);
            ps1 += __shfl_xor_sync(0xffffffffu, ps1, 1);
            ps1 += __shfl_xor_sync(0xffffffffu, ps1, 2);
            l0 = l0 * al0 + ps0;  m0 = mn0;
            l1 = l1 * al1 + ps1;  m1 = mn1;
            #pragma unroll
            for (int j = 0; j < 8; j++) {
                o[j][0] *= al0; o[j][1] *= al0;
                o[j][2] *= al1; o[j][3] *= al1;
            }

            // ---- PV (3-term split, ldmatrix.trans for V) ----
            const uint32_t vrow =
                Vh + (lane & 15) * AT_ROWB + ((lane >> 4) * 8) * 2;
            #pragma unroll
            for (int kk = 0; kk < 4; kk++) {
                uint32_t ph[4], pl[4];
                split_pack(sc[2*kk][0],   sc[2*kk][1],   ph[0], pl[0]);
                split_pack(sc[2*kk][2],   sc[2*kk][3],   ph[1], pl[1]);
                split_pack(sc[2*kk+1][0], sc[2*kk+1][1], ph[2], pl[2]);
                split_pack(sc[2*kk+1][2], sc[2*kk+1][3], ph[3], pl[3]);
                uint32_t rbase = vrow + 16 * kk * AT_ROWB;
                #pragma unroll
                for (int jp = 0; jp < 4; jp++) {
                    uint32_t bh4[4], bl4[4];
                    uint32_t ad = rbase + (16 * jp) * 2;
                    ldmx4t(bh4, ad);
                    ldmx4t(bl4, ad + AT_TILE);
                    float* o0 = o[2 * jp];
                    float* o1 = o[2 * jp + 1];
                    mma_bf16(o0[0], o0[1], o0[2], o0[3],
                             ph[0], ph[1], ph[2], ph[3], bh4[0], bh4[1]);
                    mma_bf16(o0[0], o0[1], o0[2], o0[3],
                             ph[0], ph[1], ph[2], ph[3], bl4[0], bl4[1]);
                    mma_bf16(o0[0], o0[1], o0[2], o0[3],
                             pl[0], pl[1], pl[2], pl[3], bh4[0], bh4[1]);
                    mma_bf16(o1[0], o1[1], o1[2], o1[3],
                             ph[0], ph[1], ph[2], ph[3], bh4[2], bh4[3]);
                    mma_bf16(o1[0], o1[1], o1[2], o1[3],
                             ph[0], ph[1], ph[2], ph[3], bl4[2], bl4[3]);
                    mma_bf16(o1[0], o1[1], o1[2], o1[3],
                             pl[0], pl[1], pl[2], pl[3], bh4[2], bh4[3]);
                }
            }
        }
        __syncthreads();
    }

    // ---- epilogue: O/l -> g_attn [B,T,D] ----
    float i0 = 1.f / l0, i1 = 1.f / l1;
    float* out0 = g_attn + ((size_t)(b * T_ + r0)) * D_ + h * HD_;
    float* out1 = g_attn + ((size_t)(b * T_ + r0 + 8)) * D_ + h * HD_;
    #pragma unroll
    for (int j = 0; j < 8; j++) {
        int d = 8 * j + 2 * tg;
        *(float2*)(out0 + d) = make_float2(o[j][0] * i0, o[j][1] * i0);
        *(float2*)(out1 + d) = make_float2(o[j][2] * i1, o[j][3] * i1);
    }
}

// ---------------------------------------------------------------------------
extern "C" void kernel_launch(void* const* d_in, const int* in_sizes, int n_in,
                              void* d_out, int out_size)
{
    const float* query = (const float*)d_in[0];
    const float* key   = (const float*)d_in[1];
    const float* value = (const float*)d_in[2];
    const float* Wq    = (const float*)d_in[3];
    const float* bq    = (const float*)d_in[4];
    const float* Wk    = (const float*)d_in[5];
    const float* bk    = (const float*)d_in[6];
    const float* Wv    = (const float*)d_in[7];
    const float* bv    = (const float*)d_in[8];
    const float* Wo    = (const float*)d_in[9];
    const float* bo    = (const float*)d_in[10];
    float* out = (float*)d_out;

    __nv_bfloat16 *qh, *ql, *kh, *kl, *vh, *vl;
    float* ap;
    cudaGetSymbolAddress((void**)&qh, g_qh);
    cudaGetSymbolAddress((void**)&ql, g_ql);
    cudaGetSymbolAddress((void**)&kh, g_kh);
    cudaGetSymbolAddress((void**)&kl, g_kl);
    cudaGetSymbolAddress((void**)&vh, g_vh);
    cudaGetSymbolAddress((void**)&vl, g_vl);
    cudaGetSymbolAddress((void**)&ap, g_attn);

    cudaFuncSetAttribute(gemm_mma, cudaFuncAttributeMaxDynamicSharedMemorySize,
                         GEMM_SMEM);
    cudaFuncSetAttribute(attn_mma, cudaFuncAttributeMaxDynamicSharedMemorySize,
                         AT_SMEM);

    dim3 ggrid(D_ / 128, M_ / 128);   // (8, 64)

    gemm_mma<<<ggrid, 256, GEMM_SMEM>>>(query, Wq, bq, qh, ql, nullptr, 0, SCALE_);
    gemm_mma<<<ggrid, 256, GEMM_SMEM>>>(key,   Wk, bk, kh, kl, nullptr, 0, 1.0f);
    gemm_mma<<<ggrid, 256, GEMM_SMEM>>>(value, Wv, bv, vh, vl, nullptr, 0, 1.0f);

    attn_mma<<<dim3(16, B_ * H_), 256, AT_SMEM>>>();

    gemm_mma<<<ggrid, 256, GEMM_SMEM>>>(ap, Wo, bo, nullptr, nullptr, out, 1, 1.0f);
}